// round 6
// baseline (speedup 1.0000x reference)
#include <cuda_runtime.h>
#include <cuda_bf16.h>
#include <cuda_fp16.h>
#include <cstdint>

#define N_USERS   100000
#define N_NODES   150000
#define EMB_DIM   64
#define LPN       8             // lanes per node (each lane: 8 halves = 16 B)
#define MAXE      2000000
#define NBINS     256
#define SCAN_CHUNK 1024
#define SCAN_BLOCKS ((N_NODES + SCAN_CHUNK - 1) / SCAN_CHUNK)  // 147

// ------------- static scratch (no allocations allowed) -----------------------
__device__ int    g_is64;
__device__ int    g_hist[N_NODES];
__device__ int    g_cursor[N_NODES];
__device__ int    g_off[N_NODES + 1];
__device__ int    g_part[SCAN_BLOCKS];
__device__ float  g_dis[N_NODES];             // deg_inv_sqrt
__device__ int2   g_csr[MAXE];                // (src, __float_as_int(norm))
__device__ int    g_bins[NBINS];              // degree histogram (counting sort)
__device__ int    g_binoff[NBINS];
__device__ int    g_bincur[NBINS];
__device__ int    g_order[N_NODES];           // nodes sorted by degree
// half-precision propagation buffers: 64 halves (128 B) per node row
__device__ __half g_x0[(size_t)N_NODES * EMB_DIM];
__device__ __half g_x1[(size_t)N_NODES * EMB_DIM];
__device__ __half g_x2[(size_t)N_NODES * EMB_DIM];

// ------------- helpers --------------------------------------------------------
__device__ __forceinline__ void fma8(float* acc, float w, uint4 v) {
    float2 f0 = __half22float2(*(__half2*)&v.x);
    float2 f1 = __half22float2(*(__half2*)&v.y);
    float2 f2 = __half22float2(*(__half2*)&v.z);
    float2 f3 = __half22float2(*(__half2*)&v.w);
    acc[0] = fmaf(w, f0.x, acc[0]);
    acc[1] = fmaf(w, f0.y, acc[1]);
    acc[2] = fmaf(w, f1.x, acc[2]);
    acc[3] = fmaf(w, f1.y, acc[3]);
    acc[4] = fmaf(w, f2.x, acc[4]);
    acc[5] = fmaf(w, f2.y, acc[5]);
    acc[6] = fmaf(w, f3.x, acc[6]);
    acc[7] = fmaf(w, f3.y, acc[7]);
}

__device__ __forceinline__ long long load_idx(const void* ei, int i) {
    long long v;
    if (g_is64) v = ((const long long*)ei)[i];
    else        v = (long long)((const int*)ei)[i];
    if (v < 0) v = 0;
    if (v >= N_NODES) v = N_NODES - 1;
    return v;
}

// ------------- dtype detection ------------------------------------------------
__global__ void k_detect(const long long* __restrict__ ei) {
    if (threadIdx.x == 0) {
        int ok = 1;
        for (int i = 0; i < 256; i++) {
            long long v = ei[i];
            if (v < 0 || v >= N_NODES) { ok = 0; break; }
        }
        g_is64 = ok;
    }
}

__global__ void k_zero() {
    int i = blockIdx.x * blockDim.x + threadIdx.x;
    if (i < N_NODES) { g_hist[i] = 0; g_cursor[i] = 0; }
    if (i < NBINS)   { g_bins[i] = 0; g_bincur[i] = 0; }
}

// degree histogram of col (direct dtype-branch read, no materialized idx)
__global__ void k_hist(const void* __restrict__ ei, int E) {
    int e = blockIdx.x * blockDim.x + threadIdx.x;
    if (e < E) atomicAdd(&g_hist[(int)load_idx(ei, E + e)], 1);
}

// deg_inv_sqrt + degree-value histogram for counting sort
__global__ void k_dis() {
    int i = blockIdx.x * blockDim.x + threadIdx.x;
    if (i < N_NODES) {
        int h = g_hist[i];
        g_dis[i] = (h > 0) ? rsqrtf((float)h) : 0.0f;
        int b = (h < NBINS) ? h : (NBINS - 1);
        atomicAdd(&g_bins[b], 1);
    }
}

// --- 3-pass exclusive scan of g_hist -> g_off --------------------------------
__global__ void k_partials() {
    __shared__ int s[SCAN_CHUNK];
    int idx = blockIdx.x * SCAN_CHUNK + threadIdx.x;
    s[threadIdx.x] = (idx < N_NODES) ? g_hist[idx] : 0;
    __syncthreads();
    for (int o = SCAN_CHUNK / 2; o > 0; o >>= 1) {
        if (threadIdx.x < o) s[threadIdx.x] += s[threadIdx.x + o];
        __syncthreads();
    }
    if (threadIdx.x == 0) g_part[blockIdx.x] = s[0];
}

__global__ void k_scanpart() {
    if (threadIdx.x == 0) {
        int run = 0;
        for (int b = 0; b < SCAN_BLOCKS; b++) {
            int v = g_part[b];
            g_part[b] = run;
            run += v;
        }
    }
}

__global__ void k_scanfinal() {
    __shared__ int s[SCAN_CHUNK];
    int t = threadIdx.x;
    int idx = blockIdx.x * SCAN_CHUNK + t;
    int val = (idx < N_NODES) ? g_hist[idx] : 0;
    s[t] = val;
    __syncthreads();
    for (int o = 1; o < SCAN_CHUNK; o <<= 1) {
        int v = (t >= o) ? s[t - o] : 0;
        __syncthreads();
        s[t] += v;
        __syncthreads();
    }
    int incl = s[t];
    int base = g_part[blockIdx.x];
    if (idx < N_NODES)      g_off[idx] = base + incl - val;
    if (idx == N_NODES - 1) g_off[N_NODES] = base + incl;
}

// --- exclusive scan of the 256 degree bins (single block) --------------------
__global__ void k_binscan() {
    __shared__ int s[NBINS];
    int t = threadIdx.x;
    int val = g_bins[t];
    s[t] = val;
    __syncthreads();
    for (int o = 1; o < NBINS; o <<= 1) {
        int v = (t >= o) ? s[t - o] : 0;
        __syncthreads();
        s[t] += v;
        __syncthreads();
    }
    g_binoff[t] = s[t] - val;   // exclusive
}

// --- counting-sort placement of nodes by degree (smem-aggregated atomics) ----
__global__ void k_order() {
    __shared__ int sbin[NBINS];
    __shared__ int sbase[NBINS];
    int t = threadIdx.x;
    sbin[t] = 0;                 // blockDim == 256 == NBINS
    __syncthreads();

    int node = blockIdx.x * blockDim.x + t;
    int b = -1, myrank = 0;
    if (node < N_NODES) {
        int h = g_hist[node];
        b = (h < NBINS) ? h : (NBINS - 1);
        myrank = atomicAdd(&sbin[b], 1);
    }
    __syncthreads();
    if (sbin[t] > 0) sbase[t] = atomicAdd(&g_bincur[t], sbin[t]);
    __syncthreads();
    if (node < N_NODES)
        g_order[g_binoff[b] + sbase[b] + myrank] = node;
}

// --- place edges into CSR (direct edge reads, single 8B store per edge) ------
__global__ void k_place(const void* __restrict__ ei, int E) {
    int e = blockIdx.x * blockDim.x + threadIdx.x;
    if (e >= E) return;
    int r = (int)load_idx(ei, e);
    int c = (int)load_idx(ei, E + e);
    int p = g_off[c] + atomicAdd(&g_cursor[c], 1);
    float w = g_dis[r] * g_dis[c];
    g_csr[p] = make_int2(r, __float_as_int(w));
}

// x0(half) = emb   (one thread per 4 floats)
__global__ void k_init(const float4* __restrict__ emb) {
    int i = blockIdx.x * blockDim.x + threadIdx.x;
    if (i >= N_NODES * 16) return;
    float4 v = emb[i];
    __half2 h0 = __floats2half2_rn(v.x, v.y);
    __half2 h1 = __floats2half2_rn(v.z, v.w);
    uint2 packed;
    packed.x = *(unsigned int*)&h0;
    packed.y = *(unsigned int*)&h1;
    ((uint2*)g_x0)[i] = packed;
}

// ------------- gather layer: degree-sorted nodes, 8 lanes/node, 4x unroll ----
__global__ void __launch_bounds__(256)
k_gather(const __half* __restrict__ xin, __half* __restrict__ xout) {
    int gid  = blockIdx.x * blockDim.x + threadIdx.x;
    int slot = gid >> 3;
    int lane = gid & 7;
    if (slot >= N_NODES) return;
    int node = g_order[slot];

    const uint4* __restrict__ x = (const uint4*)xin;
    int s = g_off[node];
    int e = g_off[node + 1];

    float acc[8] = {0.f, 0.f, 0.f, 0.f, 0.f, 0.f, 0.f, 0.f};
    int p = s;
    for (; p + 4 <= e; p += 4) {
        int2 e0 = __ldg(&g_csr[p]);
        int2 e1 = __ldg(&g_csr[p + 1]);
        int2 e2 = __ldg(&g_csr[p + 2]);
        int2 e3 = __ldg(&g_csr[p + 3]);
        uint4 v0 = __ldg(&x[e0.x * LPN + lane]);
        uint4 v1 = __ldg(&x[e1.x * LPN + lane]);
        uint4 v2 = __ldg(&x[e2.x * LPN + lane]);
        uint4 v3 = __ldg(&x[e3.x * LPN + lane]);
        fma8(acc, __int_as_float(e0.y), v0);
        fma8(acc, __int_as_float(e1.y), v1);
        fma8(acc, __int_as_float(e2.y), v2);
        fma8(acc, __int_as_float(e3.y), v3);
    }
    for (; p < e; p++) {
        int2 e0 = __ldg(&g_csr[p]);
        uint4 v0 = __ldg(&x[e0.x * LPN + lane]);
        fma8(acc, __int_as_float(e0.y), v0);
    }

    __half2 o0 = __floats2half2_rn(acc[0], acc[1]);
    __half2 o1 = __floats2half2_rn(acc[2], acc[3]);
    __half2 o2 = __floats2half2_rn(acc[4], acc[5]);
    __half2 o3 = __floats2half2_rn(acc[6], acc[7]);
    uint4 packed;
    packed.x = *(unsigned int*)&o0;
    packed.y = *(unsigned int*)&o1;
    packed.z = *(unsigned int*)&o2;
    packed.w = *(unsigned int*)&o3;
    ((uint4*)xout)[node * LPN + lane] = packed;
}

// ------------- final gather fused with combine -------------------------------
__global__ void __launch_bounds__(256)
k_gather_final(const __half* __restrict__ xin,      // x2
               const __half* __restrict__ x1h,
               const float4* __restrict__ emb,
               float4* __restrict__ out) {
    int gid  = blockIdx.x * blockDim.x + threadIdx.x;
    int slot = gid >> 3;
    int lane = gid & 7;
    if (slot >= N_NODES) return;
    int node = g_order[slot];

    const uint4* __restrict__ x = (const uint4*)xin;
    int s = g_off[node];
    int e = g_off[node + 1];

    float acc[8] = {0.f, 0.f, 0.f, 0.f, 0.f, 0.f, 0.f, 0.f};
    int p = s;
    for (; p + 4 <= e; p += 4) {
        int2 e0 = __ldg(&g_csr[p]);
        int2 e1 = __ldg(&g_csr[p + 1]);
        int2 e2 = __ldg(&g_csr[p + 2]);
        int2 e3 = __ldg(&g_csr[p + 3]);
        uint4 v0 = __ldg(&x[e0.x * LPN + lane]);
        uint4 v1 = __ldg(&x[e1.x * LPN + lane]);
        uint4 v2 = __ldg(&x[e2.x * LPN + lane]);
        uint4 v3 = __ldg(&x[e3.x * LPN + lane]);
        fma8(acc, __int_as_float(e0.y), v0);
        fma8(acc, __int_as_float(e1.y), v1);
        fma8(acc, __int_as_float(e2.y), v2);
        fma8(acc, __int_as_float(e3.y), v3);
    }
    for (; p < e; p++) {
        int2 e0 = __ldg(&g_csr[p]);
        uint4 v0 = __ldg(&x[e0.x * LPN + lane]);
        fma8(acc, __int_as_float(e0.y), v0);
    }

    // add own node's x1 and x2 rows
    uint4 a1 = ((const uint4*)x1h)[node * LPN + lane];
    uint4 a2 = x[node * LPN + lane];
    fma8(acc, 1.0f, a1);
    fma8(acc, 1.0f, a2);

    int fi = node * 16 + lane * 2;
    float4 e0f = emb[fi];
    float4 e1f = emb[fi + 1];
    float4 r0, r1;
    r0.x = (e0f.x + acc[0]) * 0.25f;
    r0.y = (e0f.y + acc[1]) * 0.25f;
    r0.z = (e0f.z + acc[2]) * 0.25f;
    r0.w = (e0f.w + acc[3]) * 0.25f;
    r1.x = (e1f.x + acc[4]) * 0.25f;
    r1.y = (e1f.y + acc[5]) * 0.25f;
    r1.z = (e1f.z + acc[6]) * 0.25f;
    r1.w = (e1f.w + acc[7]) * 0.25f;
    out[fi]     = r0;
    out[fi + 1] = r1;
}

// ------------- launch --------------------------------------------------------

extern "C" void kernel_launch(void* const* d_in, const int* in_sizes, int n_in,
                              void* d_out, int out_size) {
    const void*  ei  = d_in[0];
    const float* emb = (const float*)d_in[1];
    const int E = in_sizes[0] / 2;

    const int T = 256;
    const int nodeBlocks = (N_NODES + T - 1) / T;
    const int edgeBlocks = (E + T - 1) / T;
    const int initBlocks = (N_NODES * 16 + T - 1) / T;
    const int gBlocks    = (N_NODES * LPN + T - 1) / T;

    k_detect<<<1, 32>>>((const long long*)ei);
    k_zero<<<nodeBlocks, T>>>();
    k_hist<<<edgeBlocks, T>>>(ei, E);
    k_dis<<<nodeBlocks, T>>>();

    k_partials<<<SCAN_BLOCKS, SCAN_CHUNK>>>();
    k_scanpart<<<1, 32>>>();
    k_scanfinal<<<SCAN_BLOCKS, SCAN_CHUNK>>>();

    k_binscan<<<1, NBINS>>>();
    k_order<<<nodeBlocks, NBINS>>>();

    k_place<<<edgeBlocks, T>>>(ei, E);
    k_init<<<initBlocks, T>>>((const float4*)emb);

    __half *x0, *x1, *x2;
    cudaGetSymbolAddress((void**)&x0, g_x0);
    cudaGetSymbolAddress((void**)&x1, g_x1);
    cudaGetSymbolAddress((void**)&x2, g_x2);

    k_gather<<<gBlocks, T>>>(x0, x1);
    k_gather<<<gBlocks, T>>>(x1, x2);
    k_gather_final<<<gBlocks, T>>>(x2, x1, (const float4*)emb, (float4*)d_out);
}

// round 7
// speedup vs baseline: 1.3416x; 1.3416x over previous
#include <cuda_runtime.h>
#include <cuda_bf16.h>
#include <cuda_fp16.h>
#include <cstdint>

#define N_USERS   100000
#define N_NODES   150000
#define EMB_DIM   64
#define LPN       8             // lanes per node (each lane: 8 halves = 16 B)
#define MAXE      2000000
#define SCAN_CHUNK 1024
#define SCAN_BLOCKS ((N_NODES + SCAN_CHUNK - 1) / SCAN_CHUNK)  // 147

// ------------- static scratch (no allocations allowed) -----------------------
__device__ int    g_is64;
__device__ int    g_hist[N_NODES];
__device__ int    g_cursor[N_NODES];
__device__ int    g_off[N_NODES + 1];
__device__ int    g_part[SCAN_BLOCKS];
__device__ int    g_src[MAXE];                // CSR: source only (weights factored out)
// half-precision z buffers (z = deg^{-1/2} * x): 64 halves (128 B) per node row
__device__ __half g_z0[(size_t)N_NODES * EMB_DIM];
__device__ __half g_z1[(size_t)N_NODES * EMB_DIM];
__device__ __half g_z2[(size_t)N_NODES * EMB_DIM];

// ------------- helpers --------------------------------------------------------
__device__ __forceinline__ void add8(float* acc, uint4 v) {
    float2 f0 = __half22float2(*(__half2*)&v.x);
    float2 f1 = __half22float2(*(__half2*)&v.y);
    float2 f2 = __half22float2(*(__half2*)&v.z);
    float2 f3 = __half22float2(*(__half2*)&v.w);
    acc[0] += f0.x; acc[1] += f0.y;
    acc[2] += f1.x; acc[3] += f1.y;
    acc[4] += f2.x; acc[5] += f2.y;
    acc[6] += f3.x; acc[7] += f3.y;
}

__device__ __forceinline__ int load_idx(const void* ei, int i) {
    long long v;
    if (g_is64) v = ((const long long*)ei)[i];
    else        v = (long long)((const int*)ei)[i];
    if (v < 0) v = 0;
    if (v >= N_NODES) v = N_NODES - 1;
    return (int)v;
}

// ------------- dtype detection ------------------------------------------------
__global__ void k_detect(const long long* __restrict__ ei) {
    if (threadIdx.x == 0) {
        int ok = 1;
        for (int i = 0; i < 256; i++) {
            long long v = ei[i];
            if (v < 0 || v >= N_NODES) { ok = 0; break; }
        }
        g_is64 = ok;
    }
}

__global__ void k_zero() {
    int i = blockIdx.x * blockDim.x + threadIdx.x;
    if (i < N_NODES) { g_hist[i] = 0; g_cursor[i] = 0; }
}

// degree histogram of col (direct dtype-branch read)
__global__ void k_hist(const void* __restrict__ ei, int E) {
    int e = blockIdx.x * blockDim.x + threadIdx.x;
    if (e < E) atomicAdd(&g_hist[load_idx(ei, E + e)], 1);
}

// --- 3-pass exclusive scan of g_hist -> g_off --------------------------------
__global__ void k_partials() {
    __shared__ int s[SCAN_CHUNK];
    int idx = blockIdx.x * SCAN_CHUNK + threadIdx.x;
    s[threadIdx.x] = (idx < N_NODES) ? g_hist[idx] : 0;
    __syncthreads();
    for (int o = SCAN_CHUNK / 2; o > 0; o >>= 1) {
        if (threadIdx.x < o) s[threadIdx.x] += s[threadIdx.x + o];
        __syncthreads();
    }
    if (threadIdx.x == 0) g_part[blockIdx.x] = s[0];
}

__global__ void k_scanpart() {
    if (threadIdx.x == 0) {
        int run = 0;
        for (int b = 0; b < SCAN_BLOCKS; b++) {
            int v = g_part[b];
            g_part[b] = run;
            run += v;
        }
    }
}

__global__ void k_scanfinal() {
    __shared__ int s[SCAN_CHUNK];
    int t = threadIdx.x;
    int idx = blockIdx.x * SCAN_CHUNK + t;
    int val = (idx < N_NODES) ? g_hist[idx] : 0;
    s[t] = val;
    __syncthreads();
    for (int o = 1; o < SCAN_CHUNK; o <<= 1) {
        int v = (t >= o) ? s[t - o] : 0;
        __syncthreads();
        s[t] += v;
        __syncthreads();
    }
    int incl = s[t];
    int base = g_part[blockIdx.x];
    if (idx < N_NODES)      g_off[idx] = base + incl - val;
    if (idx == N_NODES - 1) g_off[N_NODES] = base + incl;
}

// --- place edges into CSR (source only, single 4B store) ---------------------
__global__ void k_place(const void* __restrict__ ei, int E) {
    int e = blockIdx.x * blockDim.x + threadIdx.x;
    if (e >= E) return;
    int r = load_idx(ei, e);
    int c = load_idx(ei, E + e);
    int p = g_off[c] + atomicAdd(&g_cursor[c], 1);
    g_src[p] = r;
}

// z0(half) = deg^{-1/2} * emb   (one thread per 4 floats)
__global__ void k_init(const float4* __restrict__ emb) {
    int i = blockIdx.x * blockDim.x + threadIdx.x;
    if (i >= N_NODES * 16) return;
    int node = i >> 4;
    int h = g_hist[node];
    float dis = (h > 0) ? rsqrtf((float)h) : 0.0f;
    float4 v = emb[i];
    __half2 h0 = __floats2half2_rn(v.x * dis, v.y * dis);
    __half2 h1 = __floats2half2_rn(v.z * dis, v.w * dis);
    uint2 packed;
    packed.x = *(unsigned int*)&h0;
    packed.y = *(unsigned int*)&h1;
    ((uint2*)g_z0)[i] = packed;
}

// ------------- gather layer: z_out[c] = (sum z_in[src]) / deg[c] -------------
// 8 lanes/node, 16B loads, 4x unroll, no per-edge weights
__global__ void __launch_bounds__(256)
k_gather(const __half* __restrict__ zin, __half* __restrict__ zout) {
    int gid  = blockIdx.x * blockDim.x + threadIdx.x;
    int node = gid >> 3;
    int lane = gid & 7;
    if (node >= N_NODES) return;

    const uint4* __restrict__ x = (const uint4*)zin;
    int s = g_off[node];
    int e = g_off[node + 1];

    float acc[8] = {0.f, 0.f, 0.f, 0.f, 0.f, 0.f, 0.f, 0.f};
    int p = s;
    for (; p + 4 <= e; p += 4) {
        int s0 = __ldg(&g_src[p]);
        int s1 = __ldg(&g_src[p + 1]);
        int s2 = __ldg(&g_src[p + 2]);
        int s3 = __ldg(&g_src[p + 3]);
        uint4 v0 = __ldg(&x[s0 * LPN + lane]);
        uint4 v1 = __ldg(&x[s1 * LPN + lane]);
        uint4 v2 = __ldg(&x[s2 * LPN + lane]);
        uint4 v3 = __ldg(&x[s3 * LPN + lane]);
        add8(acc, v0);
        add8(acc, v1);
        add8(acc, v2);
        add8(acc, v3);
    }
    for (; p < e; p++) {
        uint4 v0 = __ldg(&x[__ldg(&g_src[p]) * LPN + lane]);
        add8(acc, v0);
    }

    int deg = e - s;
    float inv = (deg > 0) ? (1.0f / (float)deg) : 0.0f;
    __half2 o0 = __floats2half2_rn(acc[0] * inv, acc[1] * inv);
    __half2 o1 = __floats2half2_rn(acc[2] * inv, acc[3] * inv);
    __half2 o2 = __floats2half2_rn(acc[4] * inv, acc[5] * inv);
    __half2 o3 = __floats2half2_rn(acc[6] * inv, acc[7] * inv);
    uint4 packed;
    packed.x = *(unsigned int*)&o0;
    packed.y = *(unsigned int*)&o1;
    packed.z = *(unsigned int*)&o2;
    packed.w = *(unsigned int*)&o3;
    ((uint4*)zout)[node * LPN + lane] = packed;
}

// ------------- final gather fused with combine -------------------------------
// S3 = sum z2[src]; x3 = S3 * rsqrt(deg); x1 = z1*sqrt(deg); x2 = z2*sqrt(deg)
// out = (emb + x1 + x2 + x3) / 4
__global__ void __launch_bounds__(256)
k_gather_final(const __half* __restrict__ z2h,
               const __half* __restrict__ z1h,
               const float4* __restrict__ emb,
               float4* __restrict__ out) {
    int gid  = blockIdx.x * blockDim.x + threadIdx.x;
    int node = gid >> 3;
    int lane = gid & 7;
    if (node >= N_NODES) return;

    const uint4* __restrict__ x = (const uint4*)z2h;
    int s = g_off[node];
    int e = g_off[node + 1];

    float acc[8] = {0.f, 0.f, 0.f, 0.f, 0.f, 0.f, 0.f, 0.f};
    int p = s;
    for (; p + 4 <= e; p += 4) {
        int s0 = __ldg(&g_src[p]);
        int s1 = __ldg(&g_src[p + 1]);
        int s2 = __ldg(&g_src[p + 2]);
        int s3 = __ldg(&g_src[p + 3]);
        uint4 v0 = __ldg(&x[s0 * LPN + lane]);
        uint4 v1 = __ldg(&x[s1 * LPN + lane]);
        uint4 v2 = __ldg(&x[s2 * LPN + lane]);
        uint4 v3 = __ldg(&x[s3 * LPN + lane]);
        add8(acc, v0);
        add8(acc, v1);
        add8(acc, v2);
        add8(acc, v3);
    }
    for (; p < e; p++) {
        uint4 v0 = __ldg(&x[__ldg(&g_src[p]) * LPN + lane]);
        add8(acc, v0);
    }

    int deg = e - s;
    float fdeg = (float)deg;
    float rsq  = (deg > 0) ? rsqrtf(fdeg) : 0.0f;   // x3 scale
    float sq   = (deg > 0) ? sqrtf(fdeg)  : 0.0f;   // x1,x2 scale

    // z1 + z2 of own node, scaled by sqrt(deg)
    uint4 a1 = ((const uint4*)z1h)[node * LPN + lane];
    uint4 a2 = x[node * LPN + lane];
    float zs[8] = {0.f, 0.f, 0.f, 0.f, 0.f, 0.f, 0.f, 0.f};
    add8(zs, a1);
    add8(zs, a2);

    int fi = node * 16 + lane * 2;
    float4 e0f = emb[fi];
    float4 e1f = emb[fi + 1];
    float4 r0, r1;
    r0.x = (e0f.x + zs[0] * sq + acc[0] * rsq) * 0.25f;
    r0.y = (e0f.y + zs[1] * sq + acc[1] * rsq) * 0.25f;
    r0.z = (e0f.z + zs[2] * sq + acc[2] * rsq) * 0.25f;
    r0.w = (e0f.w + zs[3] * sq + acc[3] * rsq) * 0.25f;
    r1.x = (e1f.x + zs[4] * sq + acc[4] * rsq) * 0.25f;
    r1.y = (e1f.y + zs[5] * sq + acc[5] * rsq) * 0.25f;
    r1.z = (e1f.z + zs[6] * sq + acc[6] * rsq) * 0.25f;
    r1.w = (e1f.w + zs[7] * sq + acc[7] * rsq) * 0.25f;
    out[fi]     = r0;
    out[fi + 1] = r1;
}

// ------------- launch --------------------------------------------------------

extern "C" void kernel_launch(void* const* d_in, const int* in_sizes, int n_in,
                              void* d_out, int out_size) {
    const void*  ei  = d_in[0];
    const float* emb = (const float*)d_in[1];
    const int E = in_sizes[0] / 2;

    const int T = 256;
    const int nodeBlocks = (N_NODES + T - 1) / T;
    const int edgeBlocks = (E + T - 1) / T;
    const int initBlocks = (N_NODES * 16 + T - 1) / T;
    const int gBlocks    = (N_NODES * LPN + T - 1) / T;

    k_detect<<<1, 32>>>((const long long*)ei);
    k_zero<<<nodeBlocks, T>>>();
    k_hist<<<edgeBlocks, T>>>(ei, E);

    k_partials<<<SCAN_BLOCKS, SCAN_CHUNK>>>();
    k_scanpart<<<1, 32>>>();
    k_scanfinal<<<SCAN_BLOCKS, SCAN_CHUNK>>>();

    k_place<<<edgeBlocks, T>>>(ei, E);
    k_init<<<initBlocks, T>>>((const float4*)emb);

    __half *z0, *z1, *z2;
    cudaGetSymbolAddress((void**)&z0, g_z0);
    cudaGetSymbolAddress((void**)&z1, g_z1);
    cudaGetSymbolAddress((void**)&z2, g_z2);

    k_gather<<<gBlocks, T>>>(z0, z1);
    k_gather<<<gBlocks, T>>>(z1, z2);
    k_gather_final<<<gBlocks, T>>>(z2, z1, (const float4*)emb, (float4*)d_out);
}

// round 9
// speedup vs baseline: 1.3599x; 1.0136x over previous
#include <cuda_runtime.h>
#include <cuda_bf16.h>
#include <cuda_fp16.h>
#include <cstdint>

#define N_USERS   100000
#define N_NODES   150000
#define EMB_DIM   64
#define LPN       8             // lanes per node (each lane: 8 halves = 16 B)
#define MAXE      2000000
#define SCAN_CHUNK 1024
#define SCAN_BLOCKS ((N_NODES + SCAN_CHUNK - 1) / SCAN_CHUNK)  // 147

// ------------- static scratch (no allocations allowed) -----------------------
__device__ int    g_is64;
__device__ int    g_hist[N_NODES];
__device__ int    g_cursor[N_NODES];
__device__ int    g_off[N_NODES + 1];
__device__ int    g_part[SCAN_BLOCKS];
__device__ int    g_src[MAXE];                // CSR: source only (weights factored out)
// half-precision z buffers (z = deg^{-1/2} * x): 64 halves (128 B) per node row
__device__ __half g_z0[(size_t)N_NODES * EMB_DIM];
__device__ __half g_z1[(size_t)N_NODES * EMB_DIM];
__device__ __half g_z2[(size_t)N_NODES * EMB_DIM];

// ------------- helpers --------------------------------------------------------
__device__ __forceinline__ void add8(float* acc, uint4 v) {
    float2 f0 = __half22float2(*(__half2*)&v.x);
    float2 f1 = __half22float2(*(__half2*)&v.y);
    float2 f2 = __half22float2(*(__half2*)&v.z);
    float2 f3 = __half22float2(*(__half2*)&v.w);
    acc[0] += f0.x; acc[1] += f0.y;
    acc[2] += f1.x; acc[3] += f1.y;
    acc[4] += f2.x; acc[5] += f2.y;
    acc[6] += f3.x; acc[7] += f3.y;
}

__device__ __forceinline__ int clampn(long long v) {
    if (v < 0) v = 0;
    if (v >= N_NODES) v = N_NODES - 1;
    return (int)v;
}

// ------------- zero + dtype detection (fused) --------------------------------
__global__ void k_zero_detect(const long long* __restrict__ ei) {
    int i = blockIdx.x * blockDim.x + threadIdx.x;
    if (i < N_NODES) { g_hist[i] = 0; g_cursor[i] = 0; }
    if (blockIdx.x == 0 && threadIdx.x == 0) {
        int ok = 1;
        for (int k = 0; k < 256; k++) {
            long long v = ei[k];
            if (v < 0 || v >= N_NODES) { ok = 0; break; }
        }
        g_is64 = ok;
    }
}

// degree histogram of col — 2 edges per thread, vectorized loads
__global__ void k_hist(const void* __restrict__ ei, int E) {
    int t = blockIdx.x * blockDim.x + threadIdx.x;
    int e = t * 2;
    if (e >= E) return;
    int c0, c1 = -1;
    if (g_is64) {
        longlong2 cc = __ldg(&((const longlong2*)ei)[(E + e) >> 1]);
        c0 = clampn(cc.x);
        if (e + 1 < E) c1 = clampn(cc.y);
    } else {
        int2 cc = __ldg(&((const int2*)ei)[(E + e) >> 1]);
        c0 = clampn((long long)cc.x);
        if (e + 1 < E) c1 = clampn((long long)cc.y);
    }
    atomicAdd(&g_hist[c0], 1);
    if (c1 >= 0) atomicAdd(&g_hist[c1], 1);
}

// --- 3-pass exclusive scan of g_hist -> g_off --------------------------------
__global__ void k_partials() {
    __shared__ int s[SCAN_CHUNK];
    int idx = blockIdx.x * SCAN_CHUNK + threadIdx.x;
    s[threadIdx.x] = (idx < N_NODES) ? g_hist[idx] : 0;
    __syncthreads();
    for (int o = SCAN_CHUNK / 2; o > 0; o >>= 1) {
        if (threadIdx.x < o) s[threadIdx.x] += s[threadIdx.x + o];
        __syncthreads();
    }
    if (threadIdx.x == 0) g_part[blockIdx.x] = s[0];
}

// parallel Hillis-Steele scan of the 147 block partials (1 block, 256 threads)
__global__ void k_scanpart() {
    __shared__ int s[256];
    int t = threadIdx.x;
    int val = (t < SCAN_BLOCKS) ? g_part[t] : 0;
    s[t] = val;
    __syncthreads();
    for (int o = 1; o < 256; o <<= 1) {
        int v = (t >= o) ? s[t - o] : 0;
        __syncthreads();
        s[t] += v;
        __syncthreads();
    }
    if (t < SCAN_BLOCKS) g_part[t] = s[t] - val;   // exclusive
}

__global__ void k_scanfinal() {
    __shared__ int s[SCAN_CHUNK];
    int t = threadIdx.x;
    int idx = blockIdx.x * SCAN_CHUNK + t;
    int val = (idx < N_NODES) ? g_hist[idx] : 0;
    s[t] = val;
    __syncthreads();
    for (int o = 1; o < SCAN_CHUNK; o <<= 1) {
        int v = (t >= o) ? s[t - o] : 0;
        __syncthreads();
        s[t] += v;
        __syncthreads();
    }
    int incl = s[t];
    int base = g_part[blockIdx.x];
    if (idx < N_NODES)      g_off[idx] = base + incl - val;
    if (idx == N_NODES - 1) g_off[N_NODES] = base + incl;
}

// --- place edges into CSR — 2 edges per thread, vectorized loads -------------
__global__ void k_place(const void* __restrict__ ei, int E) {
    int t = blockIdx.x * blockDim.x + threadIdx.x;
    int e = t * 2;
    if (e >= E) return;
    int r0, c0, r1 = -1, c1 = -1;
    if (g_is64) {
        longlong2 rr = __ldg(&((const longlong2*)ei)[e >> 1]);
        longlong2 cc = __ldg(&((const longlong2*)ei)[(E + e) >> 1]);
        r0 = clampn(rr.x); c0 = clampn(cc.x);
        if (e + 1 < E) { r1 = clampn(rr.y); c1 = clampn(cc.y); }
    } else {
        int2 rr = __ldg(&((const int2*)ei)[e >> 1]);
        int2 cc = __ldg(&((const int2*)ei)[(E + e) >> 1]);
        r0 = clampn((long long)rr.x); c0 = clampn((long long)cc.x);
        if (e + 1 < E) { r1 = clampn((long long)rr.y); c1 = clampn((long long)cc.y); }
    }
    int p0 = g_off[c0] + atomicAdd(&g_cursor[c0], 1);
    g_src[p0] = r0;
    if (r1 >= 0) {
        int p1 = g_off[c1] + atomicAdd(&g_cursor[c1], 1);
        g_src[p1] = r1;
    }
}

// z0(half) = deg^{-1/2} * emb   (one thread per 4 floats)
__global__ void k_init(const float4* __restrict__ emb) {
    int i = blockIdx.x * blockDim.x + threadIdx.x;
    if (i >= N_NODES * 16) return;
    int node = i >> 4;
    int h = g_hist[node];
    float dis = (h > 0) ? rsqrtf((float)h) : 0.0f;
    float4 v = emb[i];
    __half2 h0 = __floats2half2_rn(v.x * dis, v.y * dis);
    __half2 h1 = __floats2half2_rn(v.z * dis, v.w * dis);
    uint2 packed;
    packed.x = *(unsigned int*)&h0;
    packed.y = *(unsigned int*)&h1;
    ((uint2*)g_z0)[i] = packed;
}

// ------------- gather layer: z_out[c] = (sum z_in[src]) / deg[c] -------------
__global__ void __launch_bounds__(256)
k_gather(const __half* __restrict__ zin, __half* __restrict__ zout) {
    int gid  = blockIdx.x * blockDim.x + threadIdx.x;
    int node = gid >> 3;
    int lane = gid & 7;
    if (node >= N_NODES) return;

    const uint4* __restrict__ x = (const uint4*)zin;
    int s = g_off[node];
    int e = g_off[node + 1];

    float acc[8] = {0.f, 0.f, 0.f, 0.f, 0.f, 0.f, 0.f, 0.f};
    int p = s;
    for (; p + 4 <= e; p += 4) {
        int s0 = __ldg(&g_src[p]);
        int s1 = __ldg(&g_src[p + 1]);
        int s2 = __ldg(&g_src[p + 2]);
        int s3 = __ldg(&g_src[p + 3]);
        uint4 v0 = __ldg(&x[s0 * LPN + lane]);
        uint4 v1 = __ldg(&x[s1 * LPN + lane]);
        uint4 v2 = __ldg(&x[s2 * LPN + lane]);
        uint4 v3 = __ldg(&x[s3 * LPN + lane]);
        add8(acc, v0);
        add8(acc, v1);
        add8(acc, v2);
        add8(acc, v3);
    }
    for (; p < e; p++) {
        uint4 v0 = __ldg(&x[__ldg(&g_src[p]) * LPN + lane]);
        add8(acc, v0);
    }

    int deg = e - s;
    float inv = (deg > 0) ? (1.0f / (float)deg) : 0.0f;
    __half2 o0 = __floats2half2_rn(acc[0] * inv, acc[1] * inv);
    __half2 o1 = __floats2half2_rn(acc[2] * inv, acc[3] * inv);
    __half2 o2 = __floats2half2_rn(acc[4] * inv, acc[5] * inv);
    __half2 o3 = __floats2half2_rn(acc[6] * inv, acc[7] * inv);
    uint4 packed;
    packed.x = *(unsigned int*)&o0;
    packed.y = *(unsigned int*)&o1;
    packed.z = *(unsigned int*)&o2;
    packed.w = *(unsigned int*)&o3;
    ((uint4*)zout)[node * LPN + lane] = packed;
}

// ------------- final gather fused with combine -------------------------------
// S3 = sum z2[src]; out = (emb + (z1+z2)*sqrt(deg) + S3*rsqrt(deg)) / 4
__global__ void __launch_bounds__(256)
k_gather_final(const __half* __restrict__ z2h,
               const __half* __restrict__ z1h,
               const float4* __restrict__ emb,
               float4* __restrict__ out) {
    int gid  = blockIdx.x * blockDim.x + threadIdx.x;
    int node = gid >> 3;
    int lane = gid & 7;
    if (node >= N_NODES) return;

    const uint4* __restrict__ x = (const uint4*)z2h;
    int s = g_off[node];
    int e = g_off[node + 1];

    float acc[8] = {0.f, 0.f, 0.f, 0.f, 0.f, 0.f, 0.f, 0.f};
    int p = s;
    for (; p + 4 <= e; p += 4) {
        int s0 = __ldg(&g_src[p]);
        int s1 = __ldg(&g_src[p + 1]);
        int s2 = __ldg(&g_src[p + 2]);
        int s3 = __ldg(&g_src[p + 3]);
        uint4 v0 = __ldg(&x[s0 * LPN + lane]);
        uint4 v1 = __ldg(&x[s1 * LPN + lane]);
        uint4 v2 = __ldg(&x[s2 * LPN + lane]);
        uint4 v3 = __ldg(&x[s3 * LPN + lane]);
        add8(acc, v0);
        add8(acc, v1);
        add8(acc, v2);
        add8(acc, v3);
    }
    for (; p < e; p++) {
        uint4 v0 = __ldg(&x[__ldg(&g_src[p]) * LPN + lane]);
        add8(acc, v0);
    }

    int deg = e - s;
    float fdeg = (float)deg;
    float rsq  = (deg > 0) ? rsqrtf(fdeg) : 0.0f;   // x3 scale
    float sq   = (deg > 0) ? sqrtf(fdeg)  : 0.0f;   // x1,x2 scale

    uint4 a1 = ((const uint4*)z1h)[node * LPN + lane];
    uint4 a2 = x[node * LPN + lane];
    float zs[8] = {0.f, 0.f, 0.f, 0.f, 0.f, 0.f, 0.f, 0.f};
    add8(zs, a1);
    add8(zs, a2);

    int fi = node * 16 + lane * 2;
    float4 e0f = emb[fi];
    float4 e1f = emb[fi + 1];
    float4 r0, r1;
    r0.x = (e0f.x + zs[0] * sq + acc[0] * rsq) * 0.25f;
    r0.y = (e0f.y + zs[1] * sq + acc[1] * rsq) * 0.25f;
    r0.z = (e0f.z + zs[2] * sq + acc[2] * rsq) * 0.25f;
    r0.w = (e0f.w + zs[3] * sq + acc[3] * rsq) * 0.25f;
    r1.x = (e1f.x + zs[4] * sq + acc[4] * rsq) * 0.25f;
    r1.y = (e1f.y + zs[5] * sq + acc[5] * rsq) * 0.25f;
    r1.z = (e1f.z + zs[6] * sq + acc[6] * rsq) * 0.25f;
    r1.w = (e1f.w + zs[7] * sq + acc[7] * rsq) * 0.25f;
    out[fi]     = r0;
    out[fi + 1] = r1;
}

// ------------- launch --------------------------------------------------------

extern "C" void kernel_launch(void* const* d_in, const int* in_sizes, int n_in,
                              void* d_out, int out_size) {
    const void*  ei  = d_in[0];
    const float* emb = (const float*)d_in[1];
    const int E = in_sizes[0] / 2;

    const int T = 256;
    const int nodeBlocks  = (N_NODES + T - 1) / T;
    const int ePairBlocks = ((E + 1) / 2 + T - 1) / T;
    const int initBlocks  = (N_NODES * 16 + T - 1) / T;
    const int gBlocks     = (N_NODES * LPN + T - 1) / T;

    k_zero_detect<<<nodeBlocks, T>>>((const long long*)ei);
    k_hist<<<ePairBlocks, T>>>(ei, E);

    k_partials<<<SCAN_BLOCKS, SCAN_CHUNK>>>();
    k_scanpart<<<1, 256>>>();
    k_scanfinal<<<SCAN_BLOCKS, SCAN_CHUNK>>>();

    k_place<<<ePairBlocks, T>>>(ei, E);
    k_init<<<initBlocks, T>>>((const float4*)emb);

    __half *z0, *z1, *z2;
    cudaGetSymbolAddress((void**)&z0, g_z0);
    cudaGetSymbolAddress((void**)&z1, g_z1);
    cudaGetSymbolAddress((void**)&z2, g_z2);

    k_gather<<<gBlocks, T>>>(z0, z1);
    k_gather<<<gBlocks, T>>>(z1, z2);
    k_gather_final<<<gBlocks, T>>>(z2, z1, (const float4*)emb, (float4*)d_out);
}

// round 10
// speedup vs baseline: 1.3640x; 1.0030x over previous
#include <cuda_runtime.h>
#include <cuda_bf16.h>
#include <cuda_fp16.h>
#include <cstdint>

#define N_USERS   100000
#define N_NODES   150000
#define EMB_DIM   64
#define LPN       8             // lanes per node (each lane: 8 halves = 16 B)
#define MAXE      2000000
#define SCAN_CHUNK 1024
#define SCAN_BLOCKS ((N_NODES + SCAN_CHUNK - 1) / SCAN_CHUNK)  // 147

// ------------- static scratch (no allocations allowed) -----------------------
__device__ int                g_is64;
__device__ int                g_hist[N_NODES];
__device__ int                g_cursor[N_NODES];
__device__ int                g_off[N_NODES + 1];
__device__ unsigned long long g_agg[SCAN_BLOCKS];   // bit63=ready | aggregate
__device__ int                g_src[MAXE];          // CSR: source only
// half-precision z buffers (z = deg^{-1/2} * x): 64 halves (128 B) per node row
__device__ __half g_z0[(size_t)N_NODES * EMB_DIM];
__device__ __half g_z1[(size_t)N_NODES * EMB_DIM];
__device__ __half g_z2[(size_t)N_NODES * EMB_DIM];

// ------------- helpers --------------------------------------------------------
__device__ __forceinline__ void add8(float* acc, uint4 v) {
    float2 f0 = __half22float2(*(__half2*)&v.x);
    float2 f1 = __half22float2(*(__half2*)&v.y);
    float2 f2 = __half22float2(*(__half2*)&v.z);
    float2 f3 = __half22float2(*(__half2*)&v.w);
    acc[0] += f0.x; acc[1] += f0.y;
    acc[2] += f1.x; acc[3] += f1.y;
    acc[4] += f2.x; acc[5] += f2.y;
    acc[6] += f3.x; acc[7] += f3.y;
}

__device__ __forceinline__ int clampn(long long v) {
    if (v < 0) v = 0;
    if (v >= N_NODES) v = N_NODES - 1;
    return (int)v;
}

// ------------- zero + dtype detection (fused) --------------------------------
__global__ void k_zero_detect(const long long* __restrict__ ei) {
    int i = blockIdx.x * blockDim.x + threadIdx.x;
    if (i < N_NODES) { g_hist[i] = 0; g_cursor[i] = 0; }
    if (i < SCAN_BLOCKS) g_agg[i] = 0ULL;
    if (blockIdx.x == 0 && threadIdx.x == 0) {
        int ok = 1;
        for (int k = 0; k < 256; k++) {
            long long v = ei[k];
            if (v < 0 || v >= N_NODES) { ok = 0; break; }
        }
        g_is64 = ok;
    }
}

// degree histogram of col — 2 edges per thread, vectorized loads
__global__ void k_hist(const void* __restrict__ ei, int E) {
    int t = blockIdx.x * blockDim.x + threadIdx.x;
    int e = t * 2;
    if (e >= E) return;
    int c0, c1 = -1;
    if (g_is64) {
        longlong2 cc = __ldg(&((const longlong2*)ei)[(E + e) >> 1]);
        c0 = clampn(cc.x);
        if (e + 1 < E) c1 = clampn(cc.y);
    } else {
        int2 cc = __ldg(&((const int2*)ei)[(E + e) >> 1]);
        c0 = clampn((long long)cc.x);
        if (e + 1 < E) c1 = clampn((long long)cc.y);
    }
    atomicAdd(&g_hist[c0], 1);
    if (c1 >= 0) atomicAdd(&g_hist[c1], 1);
}

// ------------- fused scan (decoupled lookback, single wave) + z0 init --------
// 147 blocks x 1024 threads: all blocks co-resident on 148 SMs, spin is safe.
__global__ void __launch_bounds__(SCAN_CHUNK)
k_scan_init(const float4* __restrict__ emb) {
    __shared__ int   s[SCAN_CHUNK];
    __shared__ float sdis[SCAN_CHUNK];
    __shared__ int   sbase;

    int t   = threadIdx.x;
    int b   = blockIdx.x;
    int idx = b * SCAN_CHUNK + t;

    int val = (idx < N_NODES) ? g_hist[idx] : 0;
    sdis[t] = (val > 0) ? rsqrtf((float)val) : 0.0f;
    s[t] = val;
    if (t == 0) sbase = 0;
    __syncthreads();

    // inclusive Hillis-Steele scan of the chunk
    for (int o = 1; o < SCAN_CHUNK; o <<= 1) {
        int v = (t >= o) ? s[t - o] : 0;
        __syncthreads();
        s[t] += v;
        __syncthreads();
    }
    int incl  = s[t];
    int total = s[SCAN_CHUNK - 1];

    // publish this block's aggregate (bit63 = ready flag, single-word protocol)
    if (t == 0)
        atomicExch(&g_agg[b], (1ULL << 63) | (unsigned long long)(unsigned)total);

    // lookback: thread t (< b) waits for predecessor t's aggregate
    if (t < b) {
        unsigned long long w;
        do { w = atomicAdd(&g_agg[t], 0ULL); } while (!(w >> 63));
        atomicAdd(&sbase, (int)(unsigned)w);
    }
    __syncthreads();
    int base = sbase;

    if (idx < N_NODES)      g_off[idx] = base + incl - val;
    if (idx == N_NODES - 1) g_off[N_NODES] = base + incl;

    // ---- fused z0 init for this block's node chunk (coalesced) ----
    // block covers float4 indices [b*16384, b*16384 + 16384)
    int vbase = b * SCAN_CHUNK * 16;
    #pragma unroll
    for (int k = 0; k < 16; k++) {
        int local = k * SCAN_CHUNK + t;          // 0 .. 16383
        int vi = vbase + local;
        if (vi >= N_NODES * 16) break;
        float dis = sdis[local >> 4];
        float4 v = __ldg(&emb[vi]);
        __half2 h0 = __floats2half2_rn(v.x * dis, v.y * dis);
        __half2 h1 = __floats2half2_rn(v.z * dis, v.w * dis);
        uint2 packed;
        packed.x = *(unsigned int*)&h0;
        packed.y = *(unsigned int*)&h1;
        ((uint2*)g_z0)[vi] = packed;
    }
}

// --- place edges into CSR — 2 edges per thread, vectorized loads -------------
__global__ void k_place(const void* __restrict__ ei, int E) {
    int t = blockIdx.x * blockDim.x + threadIdx.x;
    int e = t * 2;
    if (e >= E) return;
    int r0, c0, r1 = -1, c1 = -1;
    if (g_is64) {
        longlong2 rr = __ldg(&((const longlong2*)ei)[e >> 1]);
        longlong2 cc = __ldg(&((const longlong2*)ei)[(E + e) >> 1]);
        r0 = clampn(rr.x); c0 = clampn(cc.x);
        if (e + 1 < E) { r1 = clampn(rr.y); c1 = clampn(cc.y); }
    } else {
        int2 rr = __ldg(&((const int2*)ei)[e >> 1]);
        int2 cc = __ldg(&((const int2*)ei)[(E + e) >> 1]);
        r0 = clampn((long long)rr.x); c0 = clampn((long long)cc.x);
        if (e + 1 < E) { r1 = clampn((long long)rr.y); c1 = clampn((long long)cc.y); }
    }
    int p0 = g_off[c0] + atomicAdd(&g_cursor[c0], 1);
    g_src[p0] = r0;
    if (r1 >= 0) {
        int p1 = g_off[c1] + atomicAdd(&g_cursor[c1], 1);
        g_src[p1] = r1;
    }
}

// ------------- gather layer: z_out[c] = (sum z_in[src]) / deg[c] -------------
__global__ void __launch_bounds__(256)
k_gather(const __half* __restrict__ zin, __half* __restrict__ zout) {
    int gid  = blockIdx.x * blockDim.x + threadIdx.x;
    int node = gid >> 3;
    int lane = gid & 7;
    if (node >= N_NODES) return;

    const uint4* __restrict__ x = (const uint4*)zin;
    int s = g_off[node];
    int e = g_off[node + 1];

    float acc[8] = {0.f, 0.f, 0.f, 0.f, 0.f, 0.f, 0.f, 0.f};
    int p = s;
    for (; p + 4 <= e; p += 4) {
        int s0 = __ldg(&g_src[p]);
        int s1 = __ldg(&g_src[p + 1]);
        int s2 = __ldg(&g_src[p + 2]);
        int s3 = __ldg(&g_src[p + 3]);
        uint4 v0 = __ldg(&x[s0 * LPN + lane]);
        uint4 v1 = __ldg(&x[s1 * LPN + lane]);
        uint4 v2 = __ldg(&x[s2 * LPN + lane]);
        uint4 v3 = __ldg(&x[s3 * LPN + lane]);
        add8(acc, v0);
        add8(acc, v1);
        add8(acc, v2);
        add8(acc, v3);
    }
    for (; p < e; p++) {
        uint4 v0 = __ldg(&x[__ldg(&g_src[p]) * LPN + lane]);
        add8(acc, v0);
    }

    int deg = e - s;
    float inv = (deg > 0) ? (1.0f / (float)deg) : 0.0f;
    __half2 o0 = __floats2half2_rn(acc[0] * inv, acc[1] * inv);
    __half2 o1 = __floats2half2_rn(acc[2] * inv, acc[3] * inv);
    __half2 o2 = __floats2half2_rn(acc[4] * inv, acc[5] * inv);
    __half2 o3 = __floats2half2_rn(acc[6] * inv, acc[7] * inv);
    uint4 packed;
    packed.x = *(unsigned int*)&o0;
    packed.y = *(unsigned int*)&o1;
    packed.z = *(unsigned int*)&o2;
    packed.w = *(unsigned int*)&o3;
    ((uint4*)zout)[node * LPN + lane] = packed;
}

// ------------- final gather fused with combine -------------------------------
// S3 = sum z2[src]; out = (emb + (z1+z2)*sqrt(deg) + S3*rsqrt(deg)) / 4
__global__ void __launch_bounds__(256)
k_gather_final(const __half* __restrict__ z2h,
               const __half* __restrict__ z1h,
               const float4* __restrict__ emb,
               float4* __restrict__ out) {
    int gid  = blockIdx.x * blockDim.x + threadIdx.x;
    int node = gid >> 3;
    int lane = gid & 7;
    if (node >= N_NODES) return;

    const uint4* __restrict__ x = (const uint4*)z2h;
    int s = g_off[node];
    int e = g_off[node + 1];

    float acc[8] = {0.f, 0.f, 0.f, 0.f, 0.f, 0.f, 0.f, 0.f};
    int p = s;
    for (; p + 4 <= e; p += 4) {
        int s0 = __ldg(&g_src[p]);
        int s1 = __ldg(&g_src[p + 1]);
        int s2 = __ldg(&g_src[p + 2]);
        int s3 = __ldg(&g_src[p + 3]);
        uint4 v0 = __ldg(&x[s0 * LPN + lane]);
        uint4 v1 = __ldg(&x[s1 * LPN + lane]);
        uint4 v2 = __ldg(&x[s2 * LPN + lane]);
        uint4 v3 = __ldg(&x[s3 * LPN + lane]);
        add8(acc, v0);
        add8(acc, v1);
        add8(acc, v2);
        add8(acc, v3);
    }
    for (; p < e; p++) {
        uint4 v0 = __ldg(&x[__ldg(&g_src[p]) * LPN + lane]);
        add8(acc, v0);
    }

    int deg = e - s;
    float fdeg = (float)deg;
    float rsq  = (deg > 0) ? rsqrtf(fdeg) : 0.0f;   // x3 scale
    float sq   = (deg > 0) ? sqrtf(fdeg)  : 0.0f;   // x1,x2 scale

    uint4 a1 = ((const uint4*)z1h)[node * LPN + lane];
    uint4 a2 = x[node * LPN + lane];
    float zs[8] = {0.f, 0.f, 0.f, 0.f, 0.f, 0.f, 0.f, 0.f};
    add8(zs, a1);
    add8(zs, a2);

    int fi = node * 16 + lane * 2;
    float4 e0f = emb[fi];
    float4 e1f = emb[fi + 1];
    float4 r0, r1;
    r0.x = (e0f.x + zs[0] * sq + acc[0] * rsq) * 0.25f;
    r0.y = (e0f.y + zs[1] * sq + acc[1] * rsq) * 0.25f;
    r0.z = (e0f.z + zs[2] * sq + acc[2] * rsq) * 0.25f;
    r0.w = (e0f.w + zs[3] * sq + acc[3] * rsq) * 0.25f;
    r1.x = (e1f.x + zs[4] * sq + acc[4] * rsq) * 0.25f;
    r1.y = (e1f.y + zs[5] * sq + acc[5] * rsq) * 0.25f;
    r1.z = (e1f.z + zs[6] * sq + acc[6] * rsq) * 0.25f;
    r1.w = (e1f.w + zs[7] * sq + acc[7] * rsq) * 0.25f;
    out[fi]     = r0;
    out[fi + 1] = r1;
}

// ------------- launch --------------------------------------------------------

extern "C" void kernel_launch(void* const* d_in, const int* in_sizes, int n_in,
                              void* d_out, int out_size) {
    const void*  ei  = d_in[0];
    const float* emb = (const float*)d_in[1];
    const int E = in_sizes[0] / 2;

    const int T = 256;
    const int nodeBlocks  = (N_NODES + T - 1) / T;
    const int ePairBlocks = ((E + 1) / 2 + T - 1) / T;
    const int gBlocks     = (N_NODES * LPN + T - 1) / T;

    k_zero_detect<<<nodeBlocks, T>>>((const long long*)ei);
    k_hist<<<ePairBlocks, T>>>(ei, E);
    k_scan_init<<<SCAN_BLOCKS, SCAN_CHUNK>>>((const float4*)emb);
    k_place<<<ePairBlocks, T>>>(ei, E);

    __half *z0, *z1, *z2;
    cudaGetSymbolAddress((void**)&z0, g_z0);
    cudaGetSymbolAddress((void**)&z1, g_z1);
    cudaGetSymbolAddress((void**)&z2, g_z2);

    k_gather<<<gBlocks, T>>>(z0, z1);
    k_gather<<<gBlocks, T>>>(z1, z2);
    k_gather_final<<<gBlocks, T>>>(z2, z1, (const float4*)emb, (float4*)d_out);
}